// round 3
// baseline (speedup 1.0000x reference)
#include <cuda_runtime.h>
#include <math.h>

// Problem constants
#define B_ 512
#define T_ 2048
#define H_ 128
#define E_ 256
#define V_ 34
#define G_ 512   // 4*H

// Output layout: (out[B,V], c[B,H], sh0[B,H], sh1[B,H], sc0[B,H], sc1[B,H], atten_vec[T])
#define OFF_OUT 0
#define OFF_C   (B_*V_)                 // 17408
#define OFF_SH0 (OFF_C   + B_*H_)       // 82944
#define OFF_SH1 (OFF_SH0 + B_*H_)       // 148480
#define OFF_SC0 (OFF_SH1 + B_*H_)       // 214016
#define OFF_SC1 (OFF_SC0 + B_*H_)       // 279552
#define OFF_ATT (OFF_SC1 + B_*H_)       // 345088

// Scratch (no allocations allowed -> __device__ globals)
__device__ float g_scores[B_*T_];   // 4 MB, softmax done in-place
__device__ float g_X[B_*G_];        // GEMM A operand (concat inputs)
__device__ float g_W[G_*G_];        // GEMM B operand (concat weights, row = gate)
__device__ float g_bias[G_];        // combined bias
__device__ float g_gates[B_*G_];    // GEMM output (gates / head pre-BN)
__device__ float g_mean[H_];
__device__ float g_var[H_];

// ---------------------------------------------------------------------------
// Concat up to 3 row-segments into g_X (toW=0) or g_W (toW=1).
// X[r][0:ka)=A[r], [ka:ka+kb)=Bp[r], [ka+kb:K)=Cp[r]
// ---------------------------------------------------------------------------
__global__ void k_concat3(const float* __restrict__ A, int ka,
                          const float* __restrict__ Bp, int kb,
                          const float* __restrict__ Cp, int kc,
                          int total, int toW) {
    int idx = blockIdx.x * blockDim.x + threadIdx.x;
    if (idx >= total) return;
    int K = ka + kb + kc;
    int r = idx / K;
    int k = idx - r * K;
    float v;
    if (k < ka)            v = A[r * ka + k];
    else if (k < ka + kb)  v = Bp[r * kb + (k - ka)];
    else                   v = Cp[r * kc + (k - ka - kb)];
    float* X = toW ? g_W : g_X;
    X[idx] = v;
}

__global__ void k_addvec(const float* __restrict__ a, const float* __restrict__ b, int n) {
    int i = blockIdx.x * blockDim.x + threadIdx.x;
    if (i < n) g_bias[i] = a[i] + b[i];
}

// ---------------------------------------------------------------------------
// C[m][n] = sum_k g_X[m][k] * g_W[n][k] + g_bias[n]
// M = 512 fixed. Tiles: BM=32, BN=64, KC=16. 256 threads, thread tile 2x4.
// Grid: (N/64, 512/32)
// ---------------------------------------------------------------------------
__global__ void k_gemm(int N, int K) {
    __shared__ float Xs[16][33];
    __shared__ float Ws[16][68];
    int tid = threadIdx.x;
    int tx = tid & 15;     // N dir (16)
    int ty = tid >> 4;     // M dir (16)
    int m0 = blockIdx.y * 32;
    int n0 = blockIdx.x * 64;

    float acc00 = 0.f, acc01 = 0.f, acc02 = 0.f, acc03 = 0.f;
    float acc10 = 0.f, acc11 = 0.f, acc12 = 0.f, acc13 = 0.f;

    int lkk = tid & 15;
    int lr  = tid >> 4;    // 0..15

    for (int k0 = 0; k0 < K; k0 += 16) {
        // Load X tile: 32 rows x 16 k
        Xs[lkk][lr]      = g_X[(m0 + lr)      * K + k0 + lkk];
        Xs[lkk][lr + 16] = g_X[(m0 + lr + 16) * K + k0 + lkk];
        // Load W tile: 64 rows x 16 k
        #pragma unroll
        for (int p = 0; p < 4; p++)
            Ws[lkk][lr + p * 16] = g_W[(n0 + lr + p * 16) * K + k0 + lkk];
        __syncthreads();

        #pragma unroll
        for (int kk = 0; kk < 16; kk++) {
            float x0 = Xs[kk][ty * 2];
            float x1 = Xs[kk][ty * 2 + 1];
            float4 wv = *(const float4*)&Ws[kk][tx * 4];
            acc00 = fmaf(x0, wv.x, acc00);
            acc01 = fmaf(x0, wv.y, acc01);
            acc02 = fmaf(x0, wv.z, acc02);
            acc03 = fmaf(x0, wv.w, acc03);
            acc10 = fmaf(x1, wv.x, acc10);
            acc11 = fmaf(x1, wv.y, acc11);
            acc12 = fmaf(x1, wv.z, acc12);
            acc13 = fmaf(x1, wv.w, acc13);
        }
        __syncthreads();
    }

    int m = m0 + ty * 2;
    int n = n0 + tx * 4;
    float b0 = g_bias[n], b1 = g_bias[n + 1], b2 = g_bias[n + 2], b3 = g_bias[n + 3];
    float* c0 = g_gates + (size_t)m * N + n;
    c0[0] = acc00 + b0; c0[1] = acc01 + b1; c0[2] = acc02 + b2; c0[3] = acc03 + b3;
    float* c1 = c0 + N;
    c1[0] = acc10 + b0; c1[1] = acc11 + b1; c1[2] = acc12 + b2; c1[3] = acc13 + b3;
}

// ---------------------------------------------------------------------------
// LSTM gate activations. gates in g_gates [B, 4H] with PyTorch order i,f,g,o.
// ---------------------------------------------------------------------------
__device__ __forceinline__ float sigm(float x) { return 1.f / (1.f + __expf(-x)); }

__global__ void k_lstm_act(const float* __restrict__ c_prev,
                           float* __restrict__ h_out, float* __restrict__ c_out) {
    int idx = blockIdx.x * blockDim.x + threadIdx.x;
    if (idx >= B_ * H_) return;
    int b = idx >> 7, h = idx & 127;
    const float* g = g_gates + (size_t)b * G_;
    float ig = sigm(g[h]);
    float fg = sigm(g[H_ + h]);
    float gg = tanhf(g[2 * H_ + h]);
    float og = sigm(g[3 * H_ + h]);
    float c = fg * c_prev[idx] + ig * gg;
    c_out[idx] = c;
    h_out[idx] = og * tanhf(c);
}

// ---------------------------------------------------------------------------
// scores[b][t] = dot(hk[b][t][:], q[b][:]).  Warp per t, float4 loads.
// Grid (B, 8), 256 threads (8 warps), each block covers 256 contiguous t.
// ---------------------------------------------------------------------------
__global__ void k_scores(const float* __restrict__ hk, const float* __restrict__ q) {
    int b = blockIdx.x;
    __shared__ float4 sq[32];
    int tid = threadIdx.x;
    if (tid < 32) sq[tid] = ((const float4*)(q + (size_t)b * H_))[tid];
    __syncthreads();
    int warp = tid >> 5, lane = tid & 31;
    float4 qv = sq[lane];
    const float4* base = (const float4*)(hk + (size_t)b * (T_ * H_));
    int t0 = blockIdx.y * 256 + warp * 32;
    #pragma unroll 4
    for (int it = 0; it < 32; it++) {
        int t = t0 + it;
        float4 v = base[(size_t)t * 32 + lane];
        float d = v.x * qv.x + v.y * qv.y + v.z * qv.z + v.w * qv.w;
        d += __shfl_xor_sync(0xffffffffu, d, 16);
        d += __shfl_xor_sync(0xffffffffu, d, 8);
        d += __shfl_xor_sync(0xffffffffu, d, 4);
        d += __shfl_xor_sync(0xffffffffu, d, 2);
        d += __shfl_xor_sync(0xffffffffu, d, 1);
        if (lane == 0) g_scores[(size_t)b * T_ + t] = d;
    }
}

// ---------------------------------------------------------------------------
// attn[b][t] = exp(s-max)*mask / sum(exp(s-max)*mask), in-place on g_scores.
// Block per b, 256 threads, 8 t per thread. Writes atten_vec (b==0).
// ---------------------------------------------------------------------------
__global__ void k_softmax(const float* __restrict__ mask, float* __restrict__ att0) {
    int b = blockIdx.x, tid = threadIdx.x;
    float* s = g_scores + (size_t)b * T_;
    const float* mk = mask + (size_t)b * T_;
    float loc[8];
    float mx = -1e30f;
    #pragma unroll
    for (int i = 0; i < 8; i++) { loc[i] = s[tid + i * 256]; mx = fmaxf(mx, loc[i]); }
    __shared__ float red[256];
    red[tid] = mx; __syncthreads();
    for (int st = 128; st > 0; st >>= 1) {
        if (tid < st) red[tid] = fmaxf(red[tid], red[tid + st]);
        __syncthreads();
    }
    mx = red[0]; __syncthreads();
    float sum = 0.f;
    #pragma unroll
    for (int i = 0; i < 8; i++) {
        float e = __expf(loc[i] - mx) * mk[tid + i * 256];
        loc[i] = e; sum += e;
    }
    red[tid] = sum; __syncthreads();
    for (int st = 128; st > 0; st >>= 1) {
        if (tid < st) red[tid] += red[tid + st];
        __syncthreads();
    }
    float inv = 1.f / red[0];
    #pragma unroll
    for (int i = 0; i < 8; i++) {
        float a = loc[i] * inv;
        s[tid + i * 256] = a;
        if (b == 0) att0[tid + i * 256] = a;
    }
}

// ---------------------------------------------------------------------------
// c[b][h] = sum_t attn[b][t] * hv[b][t][h].  Block per b, 512 threads
// (16 warps split T; lane owns 4 h via float4), attn staged in SMEM.
// ---------------------------------------------------------------------------
__global__ void k_context(const float* __restrict__ hv, float* __restrict__ c_out) {
    int b = blockIdx.x;
    __shared__ float sa[T_];
    int tid = threadIdx.x;
    for (int i = tid; i < T_; i += 512) sa[i] = g_scores[(size_t)b * T_ + i];
    __syncthreads();
    int warp = tid >> 5, lane = tid & 31;
    const float4* base = (const float4*)(hv + (size_t)b * (T_ * H_));
    float4 acc = make_float4(0.f, 0.f, 0.f, 0.f);
    #pragma unroll 4
    for (int t = warp; t < T_; t += 16) {
        float a = sa[t];
        float4 v = base[(size_t)t * 32 + lane];
        acc.x = fmaf(a, v.x, acc.x);
        acc.y = fmaf(a, v.y, acc.y);
        acc.z = fmaf(a, v.z, acc.z);
        acc.w = fmaf(a, v.w, acc.w);
    }
    __shared__ float4 part[16][32];
    part[warp][lane] = acc;
    __syncthreads();
    if (warp == 0) {
        float4 s = part[0][lane];
        #pragma unroll
        for (int w = 1; w < 16; w++) {
            float4 p = part[w][lane];
            s.x += p.x; s.y += p.y; s.z += p.z; s.w += p.w;
        }
        ((float4*)(c_out + (size_t)b * H_))[lane] = s;
    }
}

// ---------------------------------------------------------------------------
// BatchNorm training stats over batch. g_gates holds pre-BN head [B, H].
// Block per feature f, 256 threads (2 rows each).
// ---------------------------------------------------------------------------
__global__ void k_bn(void) {
    int f = blockIdx.x, tid = threadIdx.x;
    float v0 = g_gates[(size_t)tid * H_ + f];
    float v1 = g_gates[(size_t)(tid + 256) * H_ + f];
    __shared__ float rs[256], rq[256];
    rs[tid] = v0 + v1;
    rq[tid] = v0 * v0 + v1 * v1;
    __syncthreads();
    for (int st = 128; st > 0; st >>= 1) {
        if (tid < st) { rs[tid] += rs[tid + st]; rq[tid] += rq[tid + st]; }
        __syncthreads();
    }
    if (tid == 0) {
        float mn = rs[0] * (1.f / 512.f);
        g_mean[f] = mn;
        g_var[f] = rq[0] * (1.f / 512.f) - mn * mn;
    }
}

// ---------------------------------------------------------------------------
// Apply BN + ReLU then out[b][v] = relu_row . W3[v] + b3[v]. Block per b.
// ---------------------------------------------------------------------------
__global__ void k_final(const float* __restrict__ gamma, const float* __restrict__ beta,
                        const float* __restrict__ W3, const float* __restrict__ b3,
                        float* __restrict__ out) {
    int b = blockIdx.x, f = threadIdx.x;
    __shared__ float sn[H_];
    float v = g_gates[(size_t)b * H_ + f];
    float n = (v - g_mean[f]) * rsqrtf(g_var[f] + 1e-5f) * gamma[f] + beta[f];
    sn[f] = fmaxf(n, 0.f);
    __syncthreads();
    for (int vo = f; vo < V_; vo += H_) {
        float acc = b3[vo];
        const float* w = W3 + (size_t)vo * H_;
        #pragma unroll 8
        for (int k = 0; k < H_; k++) acc = fmaf(sn[k], w[k], acc);
        out[(size_t)b * V_ + vo] = acc;
    }
}

// ---------------------------------------------------------------------------
extern "C" void kernel_launch(void* const* d_in, const int* in_sizes, int n_in,
                              void* d_out_v, int out_size) {
    const float* hk    = (const float*)d_in[0];
    const float* hv    = (const float*)d_in[1];
    const float* y_1   = (const float*)d_in[2];
    const float* c_1   = (const float*)d_in[3];
    const float* sh_1  = (const float*)d_in[4];   // [2,B,H]
    const float* sc_1  = (const float*)d_in[5];   // [2,B,H]
    const float* mask  = (const float*)d_in[6];
    const float* W_ih0 = (const float*)d_in[7];   // [512, 384]
    const float* W_hh0 = (const float*)d_in[8];   // [512, 128]
    const float* b_ih0 = (const float*)d_in[9];
    const float* b_hh0 = (const float*)d_in[10];
    const float* W_ih1 = (const float*)d_in[11];  // [512, 128]
    const float* W_hh1 = (const float*)d_in[12];  // [512, 128]
    const float* b_ih1 = (const float*)d_in[13];
    const float* b_hh1 = (const float*)d_in[14];
    const float* W1    = (const float*)d_in[15];  // [128, 128]
    const float* b1    = (const float*)d_in[16];
    const float* W2    = (const float*)d_in[17];  // [128, 128]
    const float* b2    = (const float*)d_in[18];
    const float* W3    = (const float*)d_in[19];  // [34, 128]
    const float* b3    = (const float*)d_in[20];
    const float* gamma = (const float*)d_in[21];
    const float* beta  = (const float*)d_in[22];
    float* d_out = (float*)d_out_v;
    (void)in_sizes; (void)n_in; (void)out_size;

    // ---- LSTM cell 0: X0 = [y_1 | c_1 | sh_1[0]] (512x512), W = [W_ih0 | W_hh0]
    k_concat3<<<(B_*G_ + 255)/256, 256>>>(y_1, E_, c_1, H_, sh_1, H_, B_*G_, 0);
    k_concat3<<<(G_*G_ + 255)/256, 256>>>(W_ih0, E_ + H_, W_hh0, H_, nullptr, 0, G_*G_, 1);
    k_addvec<<<2, 256>>>(b_ih0, b_hh0, G_);
    k_gemm<<<dim3(G_/64, B_/32), 256>>>(G_, G_);
    k_lstm_act<<<(B_*H_)/256, 256>>>(sc_1, d_out + OFF_SH0, d_out + OFF_SC0);

    // ---- LSTM cell 1: X1 = [sh0 | sh_1[1]] (512x256), W = [W_ih1 | W_hh1]
    k_concat3<<<(B_*256 + 255)/256, 256>>>(d_out + OFF_SH0, H_, sh_1 + B_*H_, H_, nullptr, 0, B_*256, 0);
    k_concat3<<<(G_*256 + 255)/256, 256>>>(W_ih1, H_, W_hh1, H_, nullptr, 0, G_*256, 1);
    k_addvec<<<2, 256>>>(b_ih1, b_hh1, G_);
    k_gemm<<<dim3(G_/64, B_/32), 256>>>(G_, 256);
    k_lstm_act<<<(B_*H_)/256, 256>>>(sc_1 + B_*H_, d_out + OFF_SH1, d_out + OFF_SC1);

    // ---- Attention (the two HBM-bound streaming passes)
    k_scores<<<dim3(B_, 8), 256>>>(hk, d_out + OFF_SH1);
    k_softmax<<<B_, 256>>>(mask, d_out + OFF_ATT);
    k_context<<<B_, 512>>>(hv, d_out + OFF_C);

    // ---- Head: pre-BN = [sh1 | c] @ [W1 | W2]^T + (b1+b2)
    k_concat3<<<(B_*256 + 255)/256, 256>>>(d_out + OFF_SH1, H_, d_out + OFF_C, H_, nullptr, 0, B_*256, 0);
    k_concat3<<<(H_*256 + 255)/256, 256>>>(W1, H_, W2, H_, nullptr, 0, H_*256, 1);
    k_addvec<<<1, 128>>>(b1, b2, H_);
    k_gemm<<<dim3(H_/64, B_/32), 256>>>(H_, 256);
    k_bn<<<H_, 256>>>();
    k_final<<<B_, H_>>>(gamma, beta, W3, b3, d_out + OFF_OUT);
}

// round 4
// speedup vs baseline: 1.0016x; 1.0016x over previous
#include <cuda_runtime.h>
#include <math.h>

// Problem constants
#define B_ 512
#define T_ 2048
#define H_ 128
#define E_ 256
#define V_ 34
#define G_ 512   // 4*H

// Output layout: (out[B,V], c[B,H], sh0[B,H], sh1[B,H], sc0[B,H], sc1[B,H], atten_vec[T])
#define OFF_OUT 0
#define OFF_C   (B_*V_)                 // 17408
#define OFF_SH0 (OFF_C   + B_*H_)       // 82944
#define OFF_SH1 (OFF_SH0 + B_*H_)       // 148480
#define OFF_SC0 (OFF_SH1 + B_*H_)       // 214016
#define OFF_SC1 (OFF_SC0 + B_*H_)       // 279552
#define OFF_ATT (OFF_SC1 + B_*H_)       // 345088

// Scratch (no allocations allowed -> __device__ globals)
__device__ float g_scores[B_*T_];   // 4 MB, softmax done in-place
__device__ float g_X[B_*G_];        // GEMM A operand (concat inputs)
__device__ float g_W[G_*G_];        // GEMM B operand (concat weights, row = gate)
__device__ float g_bias[G_];        // combined bias
__device__ float g_gates[B_*G_];    // GEMM output (gates / head pre-BN)
__device__ float g_mean[H_];
__device__ float g_var[H_];

// ---------------------------------------------------------------------------
// Concat up to 3 row-segments into g_X (toW=0) or g_W (toW=1).
// X[r][0:ka)=A[r], [ka:ka+kb)=Bp[r], [ka+kb:K)=Cp[r]
// ---------------------------------------------------------------------------
__global__ void k_concat3(const float* __restrict__ A, int ka,
                          const float* __restrict__ Bp, int kb,
                          const float* __restrict__ Cp, int kc,
                          int total, int toW) {
    int idx = blockIdx.x * blockDim.x + threadIdx.x;
    if (idx >= total) return;
    int K = ka + kb + kc;
    int r = idx / K;
    int k = idx - r * K;
    float v;
    if (k < ka)            v = A[r * ka + k];
    else if (k < ka + kb)  v = Bp[r * kb + (k - ka)];
    else                   v = Cp[r * kc + (k - ka - kb)];
    float* X = toW ? g_W : g_X;
    X[idx] = v;
}

__global__ void k_addvec(const float* __restrict__ a, const float* __restrict__ b, int n) {
    int i = blockIdx.x * blockDim.x + threadIdx.x;
    if (i < n) g_bias[i] = a[i] + b[i];
}

// ---------------------------------------------------------------------------
// C[m][n] = sum_k g_X[m][k] * g_W[n][k] + g_bias[n]
// M = 512 fixed. Tiles: BM=32, BN=64, KC=16. 256 threads, thread tile 2x4.
// Grid: (N/64, 512/32)
// ---------------------------------------------------------------------------
__global__ void k_gemm(int N, int K) {
    __shared__ float Xs[16][33];
    __shared__ float Ws[16][68];
    int tid = threadIdx.x;
    int tx = tid & 15;     // N dir (16)
    int ty = tid >> 4;     // M dir (16)
    int m0 = blockIdx.y * 32;
    int n0 = blockIdx.x * 64;

    float acc00 = 0.f, acc01 = 0.f, acc02 = 0.f, acc03 = 0.f;
    float acc10 = 0.f, acc11 = 0.f, acc12 = 0.f, acc13 = 0.f;

    int lkk = tid & 15;
    int lr  = tid >> 4;    // 0..15

    for (int k0 = 0; k0 < K; k0 += 16) {
        // Load X tile: 32 rows x 16 k
        Xs[lkk][lr]      = g_X[(m0 + lr)      * K + k0 + lkk];
        Xs[lkk][lr + 16] = g_X[(m0 + lr + 16) * K + k0 + lkk];
        // Load W tile: 64 rows x 16 k
        #pragma unroll
        for (int p = 0; p < 4; p++)
            Ws[lkk][lr + p * 16] = g_W[(n0 + lr + p * 16) * K + k0 + lkk];
        __syncthreads();

        #pragma unroll
        for (int kk = 0; kk < 16; kk++) {
            float x0 = Xs[kk][ty * 2];
            float x1 = Xs[kk][ty * 2 + 1];
            float4 wv = *(const float4*)&Ws[kk][tx * 4];
            acc00 = fmaf(x0, wv.x, acc00);
            acc01 = fmaf(x0, wv.y, acc01);
            acc02 = fmaf(x0, wv.z, acc02);
            acc03 = fmaf(x0, wv.w, acc03);
            acc10 = fmaf(x1, wv.x, acc10);
            acc11 = fmaf(x1, wv.y, acc11);
            acc12 = fmaf(x1, wv.z, acc12);
            acc13 = fmaf(x1, wv.w, acc13);
        }
        __syncthreads();
    }

    int m = m0 + ty * 2;
    int n = n0 + tx * 4;
    float b0 = g_bias[n], b1 = g_bias[n + 1], b2 = g_bias[n + 2], b3 = g_bias[n + 3];
    float* c0 = g_gates + (size_t)m * N + n;
    c0[0] = acc00 + b0; c0[1] = acc01 + b1; c0[2] = acc02 + b2; c0[3] = acc03 + b3;
    float* c1 = c0 + N;
    c1[0] = acc10 + b0; c1[1] = acc11 + b1; c1[2] = acc12 + b2; c1[3] = acc13 + b3;
}

// ---------------------------------------------------------------------------
// LSTM gate activations. gates in g_gates [B, 4H] with PyTorch order i,f,g,o.
// ---------------------------------------------------------------------------
__device__ __forceinline__ float sigm(float x) { return 1.f / (1.f + __expf(-x)); }

__global__ void k_lstm_act(const float* __restrict__ c_prev,
                           float* __restrict__ h_out, float* __restrict__ c_out) {
    int idx = blockIdx.x * blockDim.x + threadIdx.x;
    if (idx >= B_ * H_) return;
    int b = idx >> 7, h = idx & 127;
    const float* g = g_gates + (size_t)b * G_;
    float ig = sigm(g[h]);
    float fg = sigm(g[H_ + h]);
    float gg = tanhf(g[2 * H_ + h]);
    float og = sigm(g[3 * H_ + h]);
    float c = fg * c_prev[idx] + ig * gg;
    c_out[idx] = c;
    h_out[idx] = og * tanhf(c);
}

// ---------------------------------------------------------------------------
// scores[b][t] = dot(hk[b][t][:], q[b][:]).  Warp per t, float4 loads.
// Grid (B, 8), 256 threads (8 warps), each block covers 256 contiguous t.
// ---------------------------------------------------------------------------
__global__ void k_scores(const float* __restrict__ hk, const float* __restrict__ q) {
    int b = blockIdx.x;
    __shared__ float4 sq[32];
    int tid = threadIdx.x;
    if (tid < 32) sq[tid] = ((const float4*)(q + (size_t)b * H_))[tid];
    __syncthreads();
    int warp = tid >> 5, lane = tid & 31;
    float4 qv = sq[lane];
    const float4* base = (const float4*)(hk + (size_t)b * (T_ * H_));
    int t0 = blockIdx.y * 256 + warp * 32;
    #pragma unroll 4
    for (int it = 0; it < 32; it++) {
        int t = t0 + it;
        float4 v = base[(size_t)t * 32 + lane];
        float d = v.x * qv.x + v.y * qv.y + v.z * qv.z + v.w * qv.w;
        d += __shfl_xor_sync(0xffffffffu, d, 16);
        d += __shfl_xor_sync(0xffffffffu, d, 8);
        d += __shfl_xor_sync(0xffffffffu, d, 4);
        d += __shfl_xor_sync(0xffffffffu, d, 2);
        d += __shfl_xor_sync(0xffffffffu, d, 1);
        if (lane == 0) g_scores[(size_t)b * T_ + t] = d;
    }
}

// ---------------------------------------------------------------------------
// attn[b][t] = exp(s-max)*mask / sum(exp(s-max)*mask), in-place on g_scores.
// Block per b, 256 threads, 8 t per thread. Writes atten_vec (b==0).
// ---------------------------------------------------------------------------
__global__ void k_softmax(const float* __restrict__ mask, float* __restrict__ att0) {
    int b = blockIdx.x, tid = threadIdx.x;
    float* s = g_scores + (size_t)b * T_;
    const float* mk = mask + (size_t)b * T_;
    float loc[8];
    float mx = -1e30f;
    #pragma unroll
    for (int i = 0; i < 8; i++) { loc[i] = s[tid + i * 256]; mx = fmaxf(mx, loc[i]); }
    __shared__ float red[256];
    red[tid] = mx; __syncthreads();
    for (int st = 128; st > 0; st >>= 1) {
        if (tid < st) red[tid] = fmaxf(red[tid], red[tid + st]);
        __syncthreads();
    }
    mx = red[0]; __syncthreads();
    float sum = 0.f;
    #pragma unroll
    for (int i = 0; i < 8; i++) {
        float e = __expf(loc[i] - mx) * mk[tid + i * 256];
        loc[i] = e; sum += e;
    }
    red[tid] = sum; __syncthreads();
    for (int st = 128; st > 0; st >>= 1) {
        if (tid < st) red[tid] += red[tid + st];
        __syncthreads();
    }
    float inv = 1.f / red[0];
    #pragma unroll
    for (int i = 0; i < 8; i++) {
        float a = loc[i] * inv;
        s[tid + i * 256] = a;
        if (b == 0) att0[tid + i * 256] = a;
    }
}

// ---------------------------------------------------------------------------
// c[b][h] = sum_t attn[b][t] * hv[b][t][h].  Block per b, 512 threads
// (16 warps split T; lane owns 4 h via float4), attn staged in SMEM.
// ---------------------------------------------------------------------------
__global__ void k_context(const float* __restrict__ hv, float* __restrict__ c_out) {
    int b = blockIdx.x;
    __shared__ float sa[T_];
    int tid = threadIdx.x;
    for (int i = tid; i < T_; i += 512) sa[i] = g_scores[(size_t)b * T_ + i];
    __syncthreads();
    int warp = tid >> 5, lane = tid & 31;
    const float4* base = (const float4*)(hv + (size_t)b * (T_ * H_));
    float4 acc = make_float4(0.f, 0.f, 0.f, 0.f);
    #pragma unroll 4
    for (int t = warp; t < T_; t += 16) {
        float a = sa[t];
        float4 v = base[(size_t)t * 32 + lane];
        acc.x = fmaf(a, v.x, acc.x);
        acc.y = fmaf(a, v.y, acc.y);
        acc.z = fmaf(a, v.z, acc.z);
        acc.w = fmaf(a, v.w, acc.w);
    }
    __shared__ float4 part[16][32];
    part[warp][lane] = acc;
    __syncthreads();
    if (warp == 0) {
        float4 s = part[0][lane];
        #pragma unroll
        for (int w = 1; w < 16; w++) {
            float4 p = part[w][lane];
            s.x += p.x; s.y += p.y; s.z += p.z; s.w += p.w;
        }
        ((float4*)(c_out + (size_t)b * H_))[lane] = s;
    }
}

// ---------------------------------------------------------------------------
// BatchNorm training stats over batch. g_gates holds pre-BN head [B, H].
// Block per feature f, 256 threads (2 rows each).
// ---------------------------------------------------------------------------
__global__ void k_bn(void) {
    int f = blockIdx.x, tid = threadIdx.x;
    float v0 = g_gates[(size_t)tid * H_ + f];
    float v1 = g_gates[(size_t)(tid + 256) * H_ + f];
    __shared__ float rs[256], rq[256];
    rs[tid] = v0 + v1;
    rq[tid] = v0 * v0 + v1 * v1;
    __syncthreads();
    for (int st = 128; st > 0; st >>= 1) {
        if (tid < st) { rs[tid] += rs[tid + st]; rq[tid] += rq[tid + st]; }
        __syncthreads();
    }
    if (tid == 0) {
        float mn = rs[0] * (1.f / 512.f);
        g_mean[f] = mn;
        g_var[f] = rq[0] * (1.f / 512.f) - mn * mn;
    }
}

// ---------------------------------------------------------------------------
// Apply BN + ReLU then out[b][v] = relu_row . W3[v] + b3[v]. Block per b.
// ---------------------------------------------------------------------------
__global__ void k_final(const float* __restrict__ gamma, const float* __restrict__ beta,
                        const float* __restrict__ W3, const float* __restrict__ b3,
                        float* __restrict__ out) {
    int b = blockIdx.x, f = threadIdx.x;
    __shared__ float sn[H_];
    float v = g_gates[(size_t)b * H_ + f];
    float n = (v - g_mean[f]) * rsqrtf(g_var[f] + 1e-5f) * gamma[f] + beta[f];
    sn[f] = fmaxf(n, 0.f);
    __syncthreads();
    for (int vo = f; vo < V_; vo += H_) {
        float acc = b3[vo];
        const float* w = W3 + (size_t)vo * H_;
        #pragma unroll 8
        for (int k = 0; k < H_; k++) acc = fmaf(sn[k], w[k], acc);
        out[(size_t)b * V_ + vo] = acc;
    }
}

// ---------------------------------------------------------------------------
extern "C" void kernel_launch(void* const* d_in, const int* in_sizes, int n_in,
                              void* d_out_v, int out_size) {
    const float* hk    = (const float*)d_in[0];
    const float* hv    = (const float*)d_in[1];
    const float* y_1   = (const float*)d_in[2];
    const float* c_1   = (const float*)d_in[3];
    const float* sh_1  = (const float*)d_in[4];   // [2,B,H]
    const float* sc_1  = (const float*)d_in[5];   // [2,B,H]
    const float* mask  = (const float*)d_in[6];
    const float* W_ih0 = (const float*)d_in[7];   // [512, 384]
    const float* W_hh0 = (const float*)d_in[8];   // [512, 128]
    const float* b_ih0 = (const float*)d_in[9];
    const float* b_hh0 = (const float*)d_in[10];
    const float* W_ih1 = (const float*)d_in[11];  // [512, 128]
    const float* W_hh1 = (const float*)d_in[12];  // [512, 128]
    const float* b_ih1 = (const float*)d_in[13];
    const float* b_hh1 = (const float*)d_in[14];
    const float* W1    = (const float*)d_in[15];  // [128, 128]
    const float* b1    = (const float*)d_in[16];
    const float* W2    = (const float*)d_in[17];  // [128, 128]
    const float* b2    = (const float*)d_in[18];
    const float* W3    = (const float*)d_in[19];  // [34, 128]
    const float* b3    = (const float*)d_in[20];
    const float* gamma = (const float*)d_in[21];
    const float* beta  = (const float*)d_in[22];
    float* d_out = (float*)d_out_v;
    (void)in_sizes; (void)n_in; (void)out_size;

    // ---- LSTM cell 0: X0 = [y_1 | c_1 | sh_1[0]] (512x512), W = [W_ih0 | W_hh0]
    k_concat3<<<(B_*G_ + 255)/256, 256>>>(y_1, E_, c_1, H_, sh_1, H_, B_*G_, 0);
    k_concat3<<<(G_*G_ + 255)/256, 256>>>(W_ih0, E_ + H_, W_hh0, H_, nullptr, 0, G_*G_, 1);
    k_addvec<<<2, 256>>>(b_ih0, b_hh0, G_);
    k_gemm<<<dim3(G_/64, B_/32), 256>>>(G_, G_);
    k_lstm_act<<<(B_*H_)/256, 256>>>(sc_1, d_out + OFF_SH0, d_out + OFF_SC0);

    // ---- LSTM cell 1: X1 = [sh0 | sh_1[1]] (512x256), W = [W_ih1 | W_hh1]
    k_concat3<<<(B_*256 + 255)/256, 256>>>(d_out + OFF_SH0, H_, sh_1 + B_*H_, H_, nullptr, 0, B_*256, 0);
    k_concat3<<<(G_*256 + 255)/256, 256>>>(W_ih1, H_, W_hh1, H_, nullptr, 0, G_*256, 1);
    k_addvec<<<2, 256>>>(b_ih1, b_hh1, G_);
    k_gemm<<<dim3(G_/64, B_/32), 256>>>(G_, 256);
    k_lstm_act<<<(B_*H_)/256, 256>>>(sc_1 + B_*H_, d_out + OFF_SH1, d_out + OFF_SC1);

    // ---- Attention (the two HBM-bound streaming passes)
    k_scores<<<dim3(B_, 8), 256>>>(hk, d_out + OFF_SH1);
    k_softmax<<<B_, 256>>>(mask, d_out + OFF_ATT);
    k_context<<<B_, 512>>>(hv, d_out + OFF_C);

    // ---- Head: pre-BN = [sh1 | c] @ [W1 | W2]^T + (b1+b2)
    k_concat3<<<(B_*256 + 255)/256, 256>>>(d_out + OFF_SH1, H_, d_out + OFF_C, H_, nullptr, 0, B_*256, 0);
    k_concat3<<<(H_*256 + 255)/256, 256>>>(W1, H_, W2, H_, nullptr, 0, H_*256, 1);
    k_addvec<<<1, 128>>>(b1, b2, H_);
    k_gemm<<<dim3(H_/64, B_/32), 256>>>(H_, 256);
    k_bn<<<H_, 256>>>();
    k_final<<<B_, H_>>>(gamma, beta, W3, b3, d_out + OFF_OUT);
}

// round 5
// speedup vs baseline: 1.1070x; 1.1052x over previous
#include <cuda_runtime.h>
#include <math.h>

// Problem constants
#define B_ 512
#define T_ 2048
#define H_ 128
#define E_ 256
#define V_ 34

// Output layout: (out[B,V], c[B,H], sh0[B,H], sh1[B,H], sc0[B,H], sc1[B,H], atten_vec[T])
#define OFF_OUT 0
#define OFF_C   (B_*V_)
#define OFF_SH0 (OFF_C   + B_*H_)
#define OFF_SH1 (OFF_SH0 + B_*H_)
#define OFF_SC0 (OFF_SH1 + B_*H_)
#define OFF_SC1 (OFF_SC0 + B_*H_)
#define OFF_ATT (OFF_SC1 + B_*H_)

// Scratch (__device__ globals; no allocations allowed)
__device__ float g_pre[B_*H_];   // head pre-BN output
__device__ float g_mean[H_];
__device__ float g_var[H_];

__device__ __forceinline__ float sigm(float x) { return 1.f / (1.f + __expf(-x)); }

// ---------------------------------------------------------------------------
// Fused LSTM cell: gates = [Xseg0|Xseg1|Xseg2] @ [W_ih|W_hh]^T + b_ih + b_hh,
// then i/f/g/o activations -> h_out, c_out.  No concat materialization.
//
// Tile: 32 rows (batch) x 16 h (= 64 gate-cols, interleaved col = hl*4+gate).
// Grid (H/16=8, B/32=16) = 128 blocks, 256 threads, double-buffered smem.
// Thread (tx 0..15, ty 0..15): rows m0+ty*2+{0,1}; h = h0+tx; 4 gates each.
// ---------------------------------------------------------------------------
__global__ void __launch_bounds__(256) k_lstm(
    const float* __restrict__ A, int ka,
    const float* __restrict__ Bp, int kb,
    const float* __restrict__ Cp, int kc,
    const float* __restrict__ Wih, int Kin,
    const float* __restrict__ Whh,
    const float* __restrict__ bih, const float* __restrict__ bhh,
    const float* __restrict__ c_prev,
    float* __restrict__ h_out, float* __restrict__ c_out)
{
    __shared__ float Xs[2][16][34];
    __shared__ float Ws[2][16][68];
    const int tid = threadIdx.x;
    const int tx = tid & 15, ty = tid >> 4;
    const int m0 = blockIdx.y * 32;
    const int h0 = blockIdx.x * 16;
    const int lkk = tid & 15, lr = tid >> 4;
    const int K = ka + kb + kc;
    const int nt = K >> 4;

    // W row index for each of this thread's 4 loader columns (col = lr + p*16)
    int wn[4];
    #pragma unroll
    for (int p = 0; p < 4; p++) {
        int c = lr + p * 16;
        wn[p] = (c & 3) * H_ + h0 + (c >> 2);   // gate*H + h
    }

    // prologue: tile 0 -> smem buf 0
    {
        int k = lkk;
        float x0, x1;
        if (k < ka)            { x0 = A[(m0+lr)*ka + k];            x1 = A[(m0+lr+16)*ka + k]; }
        else if (k < ka + kb)  { x0 = Bp[(m0+lr)*kb + k - ka];      x1 = Bp[(m0+lr+16)*kb + k - ka]; }
        else                   { x0 = Cp[(m0+lr)*kc + k - ka - kb]; x1 = Cp[(m0+lr+16)*kc + k - ka - kb]; }
        Xs[0][lkk][lr] = x0; Xs[0][lkk][lr+16] = x1;
        #pragma unroll
        for (int p = 0; p < 4; p++)
            Ws[0][lkk][lr + p*16] = (k < Kin) ? Wih[wn[p]*Kin + k] : Whh[wn[p]*H_ + k - Kin];
    }
    __syncthreads();

    float acc[2][4] = {};
    for (int it = 0; it < nt; it++) {
        const int cur = it & 1, nxt = cur ^ 1;
        float px0 = 0.f, px1 = 0.f, pw[4] = {0.f,0.f,0.f,0.f};
        const bool more = (it + 1 < nt);
        if (more) {
            int k = (it + 1) * 16 + lkk;
            if (k < ka)            { px0 = A[(m0+lr)*ka + k];            px1 = A[(m0+lr+16)*ka + k]; }
            else if (k < ka + kb)  { px0 = Bp[(m0+lr)*kb + k - ka];      px1 = Bp[(m0+lr+16)*kb + k - ka]; }
            else                   { px0 = Cp[(m0+lr)*kc + k - ka - kb]; px1 = Cp[(m0+lr+16)*kc + k - ka - kb]; }
            #pragma unroll
            for (int p = 0; p < 4; p++)
                pw[p] = (k < Kin) ? Wih[wn[p]*Kin + k] : Whh[wn[p]*H_ + k - Kin];
        }
        #pragma unroll
        for (int kk = 0; kk < 16; kk++) {
            float x0 = Xs[cur][kk][ty*2];
            float x1 = Xs[cur][kk][ty*2 + 1];
            float4 wv = *(const float4*)&Ws[cur][kk][tx*4];
            acc[0][0] = fmaf(x0, wv.x, acc[0][0]);
            acc[0][1] = fmaf(x0, wv.y, acc[0][1]);
            acc[0][2] = fmaf(x0, wv.z, acc[0][2]);
            acc[0][3] = fmaf(x0, wv.w, acc[0][3]);
            acc[1][0] = fmaf(x1, wv.x, acc[1][0]);
            acc[1][1] = fmaf(x1, wv.y, acc[1][1]);
            acc[1][2] = fmaf(x1, wv.z, acc[1][2]);
            acc[1][3] = fmaf(x1, wv.w, acc[1][3]);
        }
        if (more) {
            Xs[nxt][lkk][lr] = px0;
            Xs[nxt][lkk][lr+16] = px1;
            #pragma unroll
            for (int p = 0; p < 4; p++) Ws[nxt][lkk][lr + p*16] = pw[p];
            __syncthreads();
        }
    }

    // epilogue: bias + activations
    const int h = h0 + tx;
    const float bi = bih[h]          + bhh[h];
    const float bf = bih[H_ + h]     + bhh[H_ + h];
    const float bg = bih[2*H_ + h]   + bhh[2*H_ + h];
    const float bo = bih[3*H_ + h]   + bhh[3*H_ + h];
    #pragma unroll
    for (int r = 0; r < 2; r++) {
        int m = m0 + ty*2 + r;
        float ig = sigm(acc[r][0] + bi);
        float fg = sigm(acc[r][1] + bf);
        float gg = tanhf(acc[r][2] + bg);
        float og = sigm(acc[r][3] + bo);
        float cn = fg * c_prev[m*H_ + h] + ig * gg;
        c_out[m*H_ + h] = cn;
        h_out[m*H_ + h] = og * tanhf(cn);
    }
}

// ---------------------------------------------------------------------------
// Fused head GEMM: pre[m][n] = [sh1|c][m] . [W1|W2][n] + b1[n] + b2[n]
// Tile 32x64, K=256, grid (2,16), 256 threads, double-buffered.
// ---------------------------------------------------------------------------
__global__ void __launch_bounds__(256) k_head(
    const float* __restrict__ sh1, const float* __restrict__ cvec,
    const float* __restrict__ W1, const float* __restrict__ W2,
    const float* __restrict__ b1, const float* __restrict__ b2)
{
    __shared__ float Xs[2][16][34];
    __shared__ float Ws[2][16][68];
    const int tid = threadIdx.x;
    const int tx = tid & 15, ty = tid >> 4;
    const int m0 = blockIdx.y * 32;
    const int n0 = blockIdx.x * 64;
    const int lkk = tid & 15, lr = tid >> 4;
    const int nt = 256 >> 4;  // 16

    {
        int k = lkk;
        Xs[0][lkk][lr]    = sh1[(m0+lr)*H_ + k];
        Xs[0][lkk][lr+16] = sh1[(m0+lr+16)*H_ + k];
        #pragma unroll
        for (int p = 0; p < 4; p++)
            Ws[0][lkk][lr + p*16] = W1[(n0 + lr + p*16)*H_ + k];
    }
    __syncthreads();

    float acc[2][4] = {};
    for (int it = 0; it < nt; it++) {
        const int cur = it & 1, nxt = cur ^ 1;
        float px0 = 0.f, px1 = 0.f, pw[4] = {0.f,0.f,0.f,0.f};
        const bool more = (it + 1 < nt);
        if (more) {
            int k = (it + 1) * 16 + lkk;
            if (k < H_) {
                px0 = sh1[(m0+lr)*H_ + k]; px1 = sh1[(m0+lr+16)*H_ + k];
                #pragma unroll
                for (int p = 0; p < 4; p++) pw[p] = W1[(n0+lr+p*16)*H_ + k];
            } else {
                int k2 = k - H_;
                px0 = cvec[(m0+lr)*H_ + k2]; px1 = cvec[(m0+lr+16)*H_ + k2];
                #pragma unroll
                for (int p = 0; p < 4; p++) pw[p] = W2[(n0+lr+p*16)*H_ + k2];
            }
        }
        #pragma unroll
        for (int kk = 0; kk < 16; kk++) {
            float x0 = Xs[cur][kk][ty*2];
            float x1 = Xs[cur][kk][ty*2 + 1];
            float4 wv = *(const float4*)&Ws[cur][kk][tx*4];
            acc[0][0] = fmaf(x0, wv.x, acc[0][0]);
            acc[0][1] = fmaf(x0, wv.y, acc[0][1]);
            acc[0][2] = fmaf(x0, wv.z, acc[0][2]);
            acc[0][3] = fmaf(x0, wv.w, acc[0][3]);
            acc[1][0] = fmaf(x1, wv.x, acc[1][0]);
            acc[1][1] = fmaf(x1, wv.y, acc[1][1]);
            acc[1][2] = fmaf(x1, wv.z, acc[1][2]);
            acc[1][3] = fmaf(x1, wv.w, acc[1][3]);
        }
        if (more) {
            Xs[nxt][lkk][lr] = px0;
            Xs[nxt][lkk][lr+16] = px1;
            #pragma unroll
            for (int p = 0; p < 4; p++) Ws[nxt][lkk][lr + p*16] = pw[p];
            __syncthreads();
        }
    }

    const int n = n0 + tx*4;
    float bb[4];
    #pragma unroll
    for (int j = 0; j < 4; j++) bb[j] = b1[n+j] + b2[n+j];
    #pragma unroll
    for (int r = 0; r < 2; r++) {
        int m = m0 + ty*2 + r;
        #pragma unroll
        for (int j = 0; j < 4; j++)
            g_pre[(size_t)m*H_ + n + j] = acc[r][j] + bb[j];
    }
}

// ---------------------------------------------------------------------------
// Fused attention: scores + masked renormalized softmax + context, one block
// per batch row. 512 threads (16 warps). hk/hv each streamed exactly once.
// ---------------------------------------------------------------------------
__global__ void __launch_bounds__(512) k_attn(
    const float* __restrict__ hk, const float* __restrict__ hv,
    const float* __restrict__ q, const float* __restrict__ mask,
    float* __restrict__ c_out, float* __restrict__ att0)
{
    __shared__ float  sa[T_];          // scores -> attn (in place)
    __shared__ float4 sq[32];
    __shared__ float4 part[16][32];
    __shared__ float  red[512];
    const int b = blockIdx.x, tid = threadIdx.x;
    const int warp = tid >> 5, lane = tid & 31;

    if (tid < 32) sq[tid] = ((const float4*)(q + (size_t)b * H_))[tid];
    __syncthreads();
    const float4 qv = sq[lane];

    // Phase 1: scores. Warp w handles t in [w*128, (w+1)*128).
    const float4* kbase = (const float4*)(hk + (size_t)b * (T_ * H_));
    {
        const int tbeg = warp * 128;
        #pragma unroll 4
        for (int t = tbeg; t < tbeg + 128; t++) {
            float4 v = kbase[(size_t)t * 32 + lane];
            float d = v.x*qv.x + v.y*qv.y + v.z*qv.z + v.w*qv.w;
            d += __shfl_xor_sync(0xffffffffu, d, 16);
            d += __shfl_xor_sync(0xffffffffu, d, 8);
            d += __shfl_xor_sync(0xffffffffu, d, 4);
            d += __shfl_xor_sync(0xffffffffu, d, 2);
            d += __shfl_xor_sync(0xffffffffu, d, 1);
            if (lane == 0) sa[t] = d;
        }
    }
    __syncthreads();

    // Phase 2: masked, renormalized softmax (4 elems/thread)
    {
        const float* mk = mask + (size_t)b * T_;
        float loc[4];
        float mx = -1e30f;
        #pragma unroll
        for (int i = 0; i < 4; i++) { loc[i] = sa[tid + i*512]; mx = fmaxf(mx, loc[i]); }
        red[tid] = mx; __syncthreads();
        for (int st = 256; st > 0; st >>= 1) {
            if (tid < st) red[tid] = fmaxf(red[tid], red[tid + st]);
            __syncthreads();
        }
        mx = red[0]; __syncthreads();
        float sum = 0.f;
        #pragma unroll
        for (int i = 0; i < 4; i++) {
            float e = __expf(loc[i] - mx) * mk[tid + i*512];
            loc[i] = e; sum += e;
        }
        red[tid] = sum; __syncthreads();
        for (int st = 256; st > 0; st >>= 1) {
            if (tid < st) red[tid] += red[tid + st];
            __syncthreads();
        }
        const float inv = 1.f / red[0];
        #pragma unroll
        for (int i = 0; i < 4; i++) {
            float a = loc[i] * inv;
            sa[tid + i*512] = a;
            if (b == 0) att0[tid + i*512] = a;
        }
    }
    __syncthreads();

    // Phase 3: context. 16 warps split T (stride 16), lane owns 4 h (float4).
    const float4* vbase = (const float4*)(hv + (size_t)b * (T_ * H_));
    float4 acc = make_float4(0.f, 0.f, 0.f, 0.f);
    #pragma unroll 4
    for (int t = warp; t < T_; t += 16) {
        float a = sa[t];
        float4 v = vbase[(size_t)t * 32 + lane];
        acc.x = fmaf(a, v.x, acc.x);
        acc.y = fmaf(a, v.y, acc.y);
        acc.z = fmaf(a, v.z, acc.z);
        acc.w = fmaf(a, v.w, acc.w);
    }
    part[warp][lane] = acc;
    __syncthreads();
    if (warp == 0) {
        float4 s = part[0][lane];
        #pragma unroll
        for (int w = 1; w < 16; w++) {
            float4 p = part[w][lane];
            s.x += p.x; s.y += p.y; s.z += p.z; s.w += p.w;
        }
        ((float4*)(c_out + (size_t)b * H_))[lane] = s;
    }
}

// ---------------------------------------------------------------------------
// BatchNorm training stats over batch (block per feature).
// ---------------------------------------------------------------------------
__global__ void k_bn(void) {
    int f = blockIdx.x, tid = threadIdx.x;
    float v0 = g_pre[(size_t)tid * H_ + f];
    float v1 = g_pre[(size_t)(tid + 256) * H_ + f];
    __shared__ float rs[256], rq[256];
    rs[tid] = v0 + v1;
    rq[tid] = v0 * v0 + v1 * v1;
    __syncthreads();
    for (int st = 128; st > 0; st >>= 1) {
        if (tid < st) { rs[tid] += rs[tid + st]; rq[tid] += rq[tid + st]; }
        __syncthreads();
    }
    if (tid == 0) {
        float mn = rs[0] * (1.f / 512.f);
        g_mean[f] = mn;
        g_var[f] = rq[0] * (1.f / 512.f) - mn * mn;
    }
}

// ---------------------------------------------------------------------------
// BN apply + ReLU + final linear (block per b).
// ---------------------------------------------------------------------------
__global__ void k_final(const float* __restrict__ gamma, const float* __restrict__ beta,
                        const float* __restrict__ W3, const float* __restrict__ b3,
                        float* __restrict__ out) {
    int b = blockIdx.x, f = threadIdx.x;
    __shared__ float sn[H_];
    float v = g_pre[(size_t)b * H_ + f];
    float n = (v - g_mean[f]) * rsqrtf(g_var[f] + 1e-5f) * gamma[f] + beta[f];
    sn[f] = fmaxf(n, 0.f);
    __syncthreads();
    for (int vo = f; vo < V_; vo += H_) {
        float acc = b3[vo];
        const float* w = W3 + (size_t)vo * H_;
        #pragma unroll 8
        for (int k = 0; k < H_; k++) acc = fmaf(sn[k], w[k], acc);
        out[(size_t)b * V_ + vo] = acc;
    }
}

// ---------------------------------------------------------------------------
extern "C" void kernel_launch(void* const* d_in, const int* in_sizes, int n_in,
                              void* d_out_v, int out_size) {
    const float* hk    = (const float*)d_in[0];
    const float* hv    = (const float*)d_in[1];
    const float* y_1   = (const float*)d_in[2];
    const float* c_1   = (const float*)d_in[3];
    const float* sh_1  = (const float*)d_in[4];   // [2,B,H]
    const float* sc_1  = (const float*)d_in[5];   // [2,B,H]
    const float* mask  = (const float*)d_in[6];
    const float* W_ih0 = (const float*)d_in[7];   // [512, 384]
    const float* W_hh0 = (const float*)d_in[8];   // [512, 128]
    const float* b_ih0 = (const float*)d_in[9];
    const float* b_hh0 = (const float*)d_in[10];
    const float* W_ih1 = (const float*)d_in[11];  // [512, 128]
    const float* W_hh1 = (const float*)d_in[12];  // [512, 128]
    const float* b_ih1 = (const float*)d_in[13];
    const float* b_hh1 = (const float*)d_in[14];
    const float* W1    = (const float*)d_in[15];  // [128, 128]
    const float* b1    = (const float*)d_in[16];
    const float* W2    = (const float*)d_in[17];  // [128, 128]
    const float* b2    = (const float*)d_in[18];
    const float* W3    = (const float*)d_in[19];  // [34, 128]
    const float* b3    = (const float*)d_in[20];
    const float* gamma = (const float*)d_in[21];
    const float* beta  = (const float*)d_in[22];
    float* d_out = (float*)d_out_v;
    (void)in_sizes; (void)n_in; (void)out_size;

    // LSTM cell 0: X = [y_1(256) | c_1(128) | sh_1[0](128)], Kin=384
    k_lstm<<<dim3(H_/16, B_/32), 256>>>(
        y_1, E_, c_1, H_, sh_1, H_,
        W_ih0, E_ + H_, W_hh0, b_ih0, b_hh0,
        sc_1, d_out + OFF_SH0, d_out + OFF_SC0);

    // LSTM cell 1: X = [sh0(128) | sh_1[1](128)], Kin=128
    k_lstm<<<dim3(H_/16, B_/32), 256>>>(
        d_out + OFF_SH0, H_, sh_1 + B_*H_, H_, (const float*)nullptr, 0,
        W_ih1, H_, W_hh1, b_ih1, b_hh1,
        sc_1 + B_*H_, d_out + OFF_SH1, d_out + OFF_SC1);

    // Attention (fused scores + softmax + context)
    k_attn<<<B_, 512>>>(hk, hv, d_out + OFF_SH1, mask,
                        d_out + OFF_C, d_out + OFF_ATT);

    // Head
    k_head<<<dim3(2, B_/32), 256>>>(d_out + OFF_SH1, d_out + OFF_C, W1, W2, b1, b2);
    k_bn<<<H_, 256>>>();
    k_final<<<B_, H_>>>(gamma, beta, W3, b3, d_out + OFF_OUT);
}